// round 4
// baseline (speedup 1.0000x reference)
#include <cuda_runtime.h>
#include <cuda_bf16.h>
#include <cstdint>
#include <math.h>

// ---------------- problem constants ----------------
#define FDIM 221
#define BATCH 2048
#define XS 224
#define NPAD 256
#define DDIM 13
#define SDIM 26
#define EDIM 8
#define VDIM 100000
#define TRI 24531             // F*(F+1)/2 valid triangle rows
#define TRIP2 24576           // padded K (multiple of 32)
#define KSPLIT 4
#define KSPAN (TRIP2 / KSPLIT)   // 6144
#define BKC 32
#define NCHUNK (KSPAN / BKC)     // 192
#define BM 128
#define BN 64

// ---------------- smem layout (bytes) ----------------
#define APAD 40                  // bf16 elems per row: 32 data + 8 pad (80B rows, conflict-free ldmatrix)
#define ROWB (APAD * 2)          // 80
#define SA_H 0
#define SA_L (BM * ROWB)                  // 10240
#define SB_H (2 * BM * ROWB)              // 20480
#define SB_L (SB_H + BN * ROWB)           // 25600
#define STG  (SB_L + BN * ROWB)           // 30720 per stage
#define SMEM_GEMM (2 * STG)               // 61440

// ---------------- scratch (device globals; no allocation APIs) ----------------
__device__ float d_X1[BATCH * XS];
__device__ float d_X2[BATCH * XS];
__device__ __nv_bfloat16 d_Wbh1[(size_t)NPAD * TRIP2];
__device__ __nv_bfloat16 d_Wbl1[(size_t)NPAD * TRIP2];
__device__ __nv_bfloat16 d_Wbh2[(size_t)NPAD * TRIP2];
__device__ __nv_bfloat16 d_Wbl2[(size_t)NPAD * TRIP2];
__device__ float d_Yp[(size_t)KSPLIT * BATCH * NPAD];
__device__ __align__(16) int d_Tij[TRIP2];   // i | (j<<16)

// ---------------- helpers ----------------
__device__ __forceinline__ uint32_t smem_u32(const void* p) {
    uint32_t a;
    asm("{ .reg .u64 t; cvta.to.shared.u64 t, %1; cvt.u32.u64 %0, t; }" : "=r"(a) : "l"(p));
    return a;
}
__device__ __forceinline__ void cpa16(uint32_t sm, const void* g) {
    asm volatile("cp.async.cg.shared.global [%0], [%1], 16;" :: "r"(sm), "l"(g));
}
__device__ __forceinline__ void ldm4(uint32_t* r, uint32_t addr) {
    asm volatile("ldmatrix.sync.aligned.m8n8.x4.shared.b16 {%0,%1,%2,%3}, [%4];"
                 : "=r"(r[0]), "=r"(r[1]), "=r"(r[2]), "=r"(r[3]) : "r"(addr));
}
__device__ __forceinline__ void mma16816(float* d, const uint32_t* a, const uint32_t* b) {
    asm volatile(
        "mma.sync.aligned.m16n8k16.row.col.f32.bf16.bf16.f32 "
        "{%0,%1,%2,%3}, {%4,%5,%6,%7}, {%8,%9}, {%0,%1,%2,%3};"
        : "+f"(d[0]), "+f"(d[1]), "+f"(d[2]), "+f"(d[3])
        : "r"(a[0]), "r"(a[1]), "r"(a[2]), "r"(a[3]), "r"(b[0]), "r"(b[1]));
}
__device__ __forceinline__ void split_bf16(float v, __nv_bfloat16& h, __nv_bfloat16& l) {
    h = __float2bfloat16(v);
    l = __float2bfloat16(v - __bfloat162float(h));
}

// ---------------- 1) packed triangle index table ----------------
__global__ void make_pairs_kernel() {
    int tid = threadIdx.x;
    for (int i = tid; i < FDIM; i += blockDim.x) {
        int start = i * FDIM - (i * (i - 1)) / 2;
        for (int j = i; j < FDIM; j++)
            d_Tij[start + j - i] = i | (j << 16);
    }
    for (int r = TRI + tid; r < TRIP2; r += blockDim.x) d_Tij[r] = 0;
}

// ---------------- 2) fold + transpose + bf16-split W -> Wb[N=256][K=24576] hi/lo ----------------
template <int L>
__global__ void pack_kernel(const float* __restrict__ W) {
    __nv_bfloat16* Wh = (L == 0) ? d_Wbh1 : d_Wbh2;
    __nv_bfloat16* Wl = (L == 0) ? d_Wbl1 : d_Wbl2;
    __shared__ __nv_bfloat16 sh[64][33];
    __shared__ __nv_bfloat16 sl[64][33];
    const int rt = blockIdx.x;   // 32 K-rows
    const int nt = blockIdx.y;   // 64 N-cols
    const int t = threadIdx.x;   // 256
    {
        const int rr = t & 31;
        const int ng = t >> 5;
        const int r = rt * 32 + rr;
        bool valid = (r < TRI);
        int p = valid ? d_Tij[r] : 0;
        int i = p & 0xffff, j = p >> 16;
        const float* wa = W + ((size_t)i * FDIM + j) * FDIM;
        const float* wb = W + ((size_t)j * FDIM + i) * FDIM;
#pragma unroll
        for (int q = 0; q < 8; q++) {
            int n = nt * 64 + ng * 8 + q;
            float v = 0.f;
            if (valid && n < FDIM) {
                v = wa[n];
                if (i != j) v += wb[n];
            }
            __nv_bfloat16 h, l;
            split_bf16(v, h, l);
            sh[ng * 8 + q][rr] = h;
            sl[ng * 8 + q][rr] = l;
        }
    }
    __syncthreads();
    {
        const int nl = t >> 2;
        const int seg = t & 3;
        size_t base = (size_t)(nt * 64 + nl) * TRIP2 + rt * 32 + seg * 8;
#pragma unroll
        for (int u = 0; u < 8; u += 2) {
            __nv_bfloat162 vh, vl;
            vh.x = sh[nl][seg * 8 + u]; vh.y = sh[nl][seg * 8 + u + 1];
            vl.x = sl[nl][seg * 8 + u]; vl.y = sl[nl][seg * 8 + u + 1];
            *(__nv_bfloat162*)(&Wh[base + u]) = vh;
            *(__nv_bfloat162*)(&Wl[base + u]) = vl;
        }
    }
}

// ---------------- 3) build x = [dense | emb] ----------------
__global__ void build_x_kernel(const float* __restrict__ dense,
                               const int* __restrict__ sparse,
                               const float* __restrict__ emb) {
    int b = blockIdx.x;
    int t = threadIdx.x;
    float v = 0.f;
    if (t < DDIM) {
        v = dense[b * DDIM + t];
    } else if (t < FDIM) {
        int q = t - DDIM;
        int s = q >> 3;
        int e = q & 7;
        int idx = sparse[b * SDIM + s];
        v = emb[((size_t)s * VDIM + idx) * EDIM + e];
    }
    d_X1[b * XS + t] = v;
}

// ---------------- 4) HMMA GEMM: Yp[split] = A(on-the-fly) x Wb^T, 3-pass bf16 hi/lo ----------------
template <int L>
__global__ void __launch_bounds__(256, 2) gemm_kernel() {
    const float* __restrict__ X = (L == 0) ? d_X1 : d_X2;
    const __nv_bfloat16* __restrict__ Wh = (L == 0) ? d_Wbh1 : d_Wbh2;
    const __nv_bfloat16* __restrict__ Wl = (L == 0) ? d_Wbl1 : d_Wbl2;
    extern __shared__ __align__(16) char smem[];
    const uint32_t sb = smem_u32(smem);

    const int tid = threadIdx.x;
    const int wid = tid >> 5;
    const int lid = tid & 31;
    const int mBase = blockIdx.x * BM;
    const int nBase = blockIdx.y * BN;
    const int split = blockIdx.z;
    const int kBase = split * KSPAN;

    // ---- producers ----
    // B via cp.async: thread -> (row = tid>>2, seg = tid&3), hi + lo
    const int brow = tid >> 2;
    const int bseg = tid & 3;
    const char* gBh = (const char*)(Wh + (size_t)(nBase + brow) * TRIP2) + bseg * 16;
    const char* gBl = (const char*)(Wl + (size_t)(nBase + brow) * TRIP2) + bseg * 16;
    const uint32_t sBoff = (uint32_t)(brow * ROWB + bseg * 16);

    auto issueB = [&](int ch, int stg) {
        size_t ko = (size_t)(kBase + ch * BKC) * 2;  // bytes
        uint32_t s0 = sb + stg * STG;
        cpa16(s0 + SB_H + sBoff, gBh + ko);
        cpa16(s0 + SB_L + sBoff, gBl + ko);
        asm volatile("cp.async.commit_group;");
    };

    // A build: thread -> (m = tid>>1, k-half = tid&1)
    const int am = tid >> 1;
    const int ak0 = (tid & 1) * 16;
    const float* xr = X + (size_t)(mBase + am) * XS;

    auto buildA = [&](int ch, int stg) {
        const int rbase = kBase + ch * BKC + ak0;
        int pp[16];
        const int4* t4 = (const int4*)(d_Tij + rbase);
#pragma unroll
        for (int q = 0; q < 4; q++) {
            int4 p = __ldg(&t4[q]);
            pp[q * 4 + 0] = p.x; pp[q * 4 + 1] = p.y;
            pp[q * 4 + 2] = p.z; pp[q * 4 + 3] = p.w;
        }
        uint32_t hw[8], lw[8];
#pragma unroll
        for (int u = 0; u < 8; u++) {
            float v0 = 0.f, v1 = 0.f;
            int r0 = rbase + 2 * u;
            int p0 = pp[2 * u], p1 = pp[2 * u + 1];
            if (r0 < TRI)     v0 = __ldg(xr + (p0 & 0xffff)) * __ldg(xr + (p0 >> 16));
            if (r0 + 1 < TRI) v1 = __ldg(xr + (p1 & 0xffff)) * __ldg(xr + (p1 >> 16));
            __nv_bfloat16 h0, l0, h1, l1;
            split_bf16(v0, h0, l0);
            split_bf16(v1, h1, l1);
            hw[u] = (uint32_t)__bfloat16_as_ushort(h0) | ((uint32_t)__bfloat16_as_ushort(h1) << 16);
            lw[u] = (uint32_t)__bfloat16_as_ushort(l0) | ((uint32_t)__bfloat16_as_ushort(l1) << 16);
        }
        char* base = smem + stg * STG;
        uint4* dh = (uint4*)(base + SA_H + am * ROWB + ak0 * 2);
        uint4* dl = (uint4*)(base + SA_L + am * ROWB + ak0 * 2);
        dh[0] = make_uint4(hw[0], hw[1], hw[2], hw[3]);
        dh[1] = make_uint4(hw[4], hw[5], hw[6], hw[7]);
        dl[0] = make_uint4(lw[0], lw[1], lw[2], lw[3]);
        dl[1] = make_uint4(lw[4], lw[5], lw[6], lw[7]);
    };

    // ---- consumer frags/accums ----
    const int wm = wid & 3;   // 4 warps in M (32 each)
    const int wn = wid >> 2;  // 2 warps in N (32 each)
    float acc[2][4][4];
#pragma unroll
    for (int a = 0; a < 2; a++)
#pragma unroll
        for (int b = 0; b < 4; b++)
#pragma unroll
            for (int c = 0; c < 4; c++) acc[a][b][c] = 0.f;

    // ldmatrix lane offsets (in bytes, within operand block)
    const int aRow = (lid & 7) + ((lid >> 3) & 1) * 8;       // + mt*16 + wm*32
    const int aCol = (lid >> 4) * 8;                          // + k16*16
    const int bRowHalf = (lid >> 4);                          // + g*2 -> n-block
    const int bRow = (lid & 7);
    const int bCol = ((lid >> 3) & 1) * 8;                    // + k16*16

    // ---- prologue ----
    issueB(0, 0);
    buildA(0, 0);
    asm volatile("cp.async.wait_group 0;");
    __syncthreads();

    for (int ch = 0; ch < NCHUNK; ch++) {
        const int buf = ch & 1;
        const bool hasNext = (ch + 1 < NCHUNK);
        if (hasNext) {
            issueB(ch + 1, buf ^ 1);
            buildA(ch + 1, buf ^ 1);
        }
        const uint32_t s0 = sb + buf * STG;
#pragma unroll
        for (int k16 = 0; k16 < 2; k16++) {
            const int kc = k16 * 16;
            uint32_t ah[2][4], al[2][4], bh[4][2], bl[4][2];
#pragma unroll
            for (int mt = 0; mt < 2; mt++) {
                uint32_t ra = (uint32_t)((wm * 32 + mt * 16 + aRow) * ROWB + (kc + aCol) * 2);
                ldm4(ah[mt], s0 + SA_H + ra);
                ldm4(al[mt], s0 + SA_L + ra);
            }
#pragma unroll
            for (int g = 0; g < 2; g++) {
                uint32_t rb = (uint32_t)((wn * 32 + (g * 2 + bRowHalf) * 8 + bRow) * ROWB + (kc + bCol) * 2);
                uint32_t t[4];
                ldm4(t, s0 + SB_H + rb);
                bh[g * 2][0] = t[0]; bh[g * 2][1] = t[1];
                bh[g * 2 + 1][0] = t[2]; bh[g * 2 + 1][1] = t[3];
                ldm4(t, s0 + SB_L + rb);
                bl[g * 2][0] = t[0]; bl[g * 2][1] = t[1];
                bl[g * 2 + 1][0] = t[2]; bl[g * 2 + 1][1] = t[3];
            }
#pragma unroll
            for (int mt = 0; mt < 2; mt++)
#pragma unroll
                for (int nt = 0; nt < 4; nt++) {
                    mma16816(acc[mt][nt], ah[mt], bh[nt]);   // Ah*Wh
                    mma16816(acc[mt][nt], ah[mt], bl[nt]);   // Ah*Wl
                    mma16816(acc[mt][nt], al[mt], bh[nt]);   // Al*Wh
                }
        }
        if (hasNext) asm volatile("cp.async.wait_group 0;");
        __syncthreads();
    }

    // ---- epilogue: deterministic split-K partials ----
    float* Yb = d_Yp + (size_t)split * BATCH * NPAD;
#pragma unroll
    for (int mt = 0; mt < 2; mt++) {
        const int m = mBase + wm * 32 + mt * 16 + (lid >> 2);
#pragma unroll
        for (int nt = 0; nt < 4; nt++) {
            const int n = nBase + wn * 32 + nt * 8 + 2 * (lid & 3);
            float2 v0 = make_float2(acc[mt][nt][0], acc[mt][nt][1]);
            float2 v1 = make_float2(acc[mt][nt][2], acc[mt][nt][3]);
            *(float2*)(Yb + (size_t)m * NPAD + n) = v0;
            *(float2*)(Yb + (size_t)(m + 8) * NPAD + n) = v1;
        }
    }
}

// ---------------- 5) reduce split-K partials + bias -> X2 ----------------
__global__ void reduce1_kernel(const float* __restrict__ b1) {
    int m = blockIdx.x;
    int c = threadIdx.x;
    float v = 0.f;
    if (c < FDIM) {
        v = b1[c];
#pragma unroll
        for (int p = 0; p < KSPLIT; p++)
            v += d_Yp[((size_t)p * BATCH + m) * NPAD + c];
    }
    d_X2[m * XS + c] = v;
}

// ---------------- 6) final: reduce + row-sum + sigmoid (softmax over size-1 axis == identity) ----------------
__global__ void final_kernel(const float* __restrict__ b2,
                             const float* __restrict__ out_w,
                             const float* __restrict__ out_b,
                             float* __restrict__ out) {
    int warp = threadIdx.x >> 5;
    int lane = threadIdx.x & 31;
    int m = blockIdx.x * 8 + warp;
    float sum = 0.f;
    for (int c = lane; c < FDIM; c += 32) {
        float t = b2[c];
#pragma unroll
        for (int p = 0; p < KSPLIT; p++)
            t += d_Yp[((size_t)p * BATCH + m) * NPAD + c];
        sum += t;
    }
#pragma unroll
    for (int o = 16; o > 0; o >>= 1) sum += __shfl_down_sync(0xffffffffu, sum, o);
    if (lane == 0) {
        float z = sum * out_w[0] + out_b[0];
        out[m] = 1.f / (1.f + expf(-z));
    }
}

extern "C" void kernel_launch(void* const* d_in, const int* in_sizes, int n_in,
                              void* d_out, int out_size) {
    const float* dense = (const float*)d_in[0];
    const int* sparse = (const int*)d_in[1];
    const float* emb = (const float*)d_in[2];
    const float* W1 = (const float*)d_in[3];
    const float* b1 = (const float*)d_in[4];
    const float* W2 = (const float*)d_in[5];
    const float* b2 = (const float*)d_in[6];
    // d_in[7..10]: attention weights — mathematically dead (softmax over size-1 axis == 1)
    const float* out_w = (const float*)d_in[11];
    const float* out_b = (const float*)d_in[12];
    float* out = (float*)d_out;

    cudaFuncSetAttribute(gemm_kernel<0>, cudaFuncAttributeMaxDynamicSharedMemorySize, SMEM_GEMM);
    cudaFuncSetAttribute(gemm_kernel<1>, cudaFuncAttributeMaxDynamicSharedMemorySize, SMEM_GEMM);

    make_pairs_kernel<<<1, 256>>>();
    pack_kernel<0><<<dim3(TRIP2 / 32, 4), 256>>>(W1);
    pack_kernel<1><<<dim3(TRIP2 / 32, 4), 256>>>(W2);
    build_x_kernel<<<BATCH, XS>>>(dense, sparse, emb);

    dim3 ggrid(BATCH / BM, NPAD / BN, KSPLIT);   // 16 x 4 x 4 = 256 CTAs
    gemm_kernel<0><<<ggrid, 256, SMEM_GEMM>>>();
    reduce1_kernel<<<BATCH, XS>>>(b1);
    gemm_kernel<1><<<ggrid, 256, SMEM_GEMM>>>();
    final_kernel<<<BATCH / 8, 256>>>(b2, out_w, out_b, out);
}

// round 5
// speedup vs baseline: 2.2793x; 2.2793x over previous
#include <cuda_runtime.h>
#include <cstdint>
#include <math.h>

// ---------------- problem constants ----------------
#define FDIM 221
#define BATCH 2048
#define XS 224
#define NPAD 256
#define DDIM 13
#define SDIM 26
#define EDIM 8
#define VDIM 100000
#define TRI 24531             // F*(F+1)/2 valid triangle rows
#define TRIP2 24544           // padded K, multiple of 32
#define BKC 32
#define CHUNKS (TRIP2 / BKC)  // 767
#define KSPLIT 9
#define CPS 86                // ceil(767/9)
#define BM 64

// ---------------- gemm smem layout (dynamic) ----------------
#define W_STG (BKC * NPAD * 4)          // 32768 B
#define A_STG (BKC * BM * 8)            // 16384 B (f32x2 duplicated pairs)
#define OFF_W0 0
#define OFF_W1 W_STG
#define OFF_A0 (2 * W_STG)
#define OFF_A1 (2 * W_STG + A_STG)
#define SMEM_GEMM (2 * W_STG + 2 * A_STG)   // 98304 B

// ---------------- scratch (device globals; no allocation APIs) ----------------
__device__ float d_X1[BATCH * XS];
__device__ float d_X2[BATCH * XS];
__device__ float d_Wp1[(size_t)TRIP2 * NPAD];          // 25.1 MB folded W1
__device__ float d_Yp[(size_t)KSPLIT * BATCH * NPAD];  // 18.9 MB split-K partials
__device__ float d_w2t[TRIP2];                         // folded column-sums of W2
__device__ float d_b2s;
__device__ __align__(16) int d_Tij[TRIP2];             // i | (j<<16)

// ---------------- helpers ----------------
__device__ __forceinline__ uint32_t smem_u32(const void* p) {
    uint32_t a;
    asm("{ .reg .u64 t; cvta.to.shared.u64 t, %1; cvt.u32.u64 %0, t; }" : "=r"(a) : "l"(p));
    return a;
}
__device__ __forceinline__ void cpa16(uint32_t sm, const void* g) {
    asm volatile("cp.async.cg.shared.global [%0], [%1], 16;" :: "r"(sm), "l"(g));
}
__device__ __forceinline__ void fma2(unsigned long long& acc,
                                     unsigned long long a,
                                     unsigned long long b) {
    asm("fma.rn.f32x2 %0, %1, %2, %0;" : "+l"(acc) : "l"(a), "l"(b));
}
__device__ __forceinline__ float2 unpack2f(unsigned long long v) {
    float2 f;
    asm("mov.b64 {%0, %1}, %2;" : "=f"(f.x), "=f"(f.y) : "l"(v));
    return f;
}

// ---------------- 1) packed triangle index table ----------------
__global__ void make_pairs_kernel() {
    int tid = threadIdx.x;
    for (int i = tid; i < FDIM; i += blockDim.x) {
        int start = i * FDIM - (i * (i - 1)) / 2;
        for (int j = i; j < FDIM; j++)
            d_Tij[start + j - i] = i | (j << 16);
    }
    for (int r = TRI + tid; r < TRIP2; r += blockDim.x) d_Tij[r] = 0;
}

// ---------------- 2) fold W1 -> Wp1[TRIP2][256] ----------------
__global__ void pack1_kernel(const float* __restrict__ W) {
    int r = blockIdx.x;
    float* dst = d_Wp1 + (size_t)r * NPAD;
    if (r >= TRI) {
        for (int c = threadIdx.x; c < NPAD; c += blockDim.x) dst[c] = 0.f;
        return;
    }
    int p = d_Tij[r];
    int i = p & 0xffff, j = p >> 16;
    const float* wa = W + ((size_t)i * FDIM + j) * FDIM;
    const float* wb = W + ((size_t)j * FDIM + i) * FDIM;
    for (int c = threadIdx.x; c < NPAD; c += blockDim.x) {
        float v = 0.f;
        if (c < FDIM) {
            v = wa[c];
            if (i != j) v += wb[c];
        }
        dst[c] = v;
    }
}

// ---------------- 3) fold column-sums of W2 -> w2t (layer 2 collapses to a quadratic form) ----------------
__global__ void w2sum_kernel(const float* __restrict__ W2) {
    int r = blockIdx.x * 8 + (threadIdx.x >> 5);
    int lane = threadIdx.x & 31;
    if (r >= TRIP2) return;
    float s = 0.f;
    if (r < TRI) {
        int p = d_Tij[r];
        int i = p & 0xffff, j = p >> 16;
        const float* wa = W2 + ((size_t)i * FDIM + j) * FDIM;
        const float* wb = W2 + ((size_t)j * FDIM + i) * FDIM;
        for (int f = lane; f < FDIM; f += 32) {
            s += wa[f];
            if (i != j) s += wb[f];
        }
    }
#pragma unroll
    for (int o = 16; o > 0; o >>= 1) s += __shfl_down_sync(0xffffffffu, s, o);
    if (lane == 0) d_w2t[r] = s;
}
__global__ void b2sum_kernel(const float* __restrict__ b2) {
    __shared__ float red[8];
    int lane = threadIdx.x & 31, warp = threadIdx.x >> 5;
    float s = 0.f;
    for (int f = threadIdx.x; f < FDIM; f += 256) s += b2[f];
#pragma unroll
    for (int o = 16; o > 0; o >>= 1) s += __shfl_down_sync(0xffffffffu, s, o);
    if (lane == 0) red[warp] = s;
    __syncthreads();
    if (threadIdx.x == 0) {
        float t = 0.f;
#pragma unroll
        for (int w = 0; w < 8; w++) t += red[w];
        d_b2s = t;
    }
}

// ---------------- 4) build x = [dense | emb] ----------------
__global__ void build_x_kernel(const float* __restrict__ dense,
                               const int* __restrict__ sparse,
                               const float* __restrict__ emb) {
    int b = blockIdx.x;
    int t = threadIdx.x;
    float v = 0.f;
    if (t < DDIM) {
        v = dense[b * DDIM + t];
    } else if (t < FDIM) {
        int q = t - DDIM;
        int s = q >> 3;
        int e = q & 7;
        int idx = sparse[b * SDIM + s];
        v = emb[((size_t)s * VDIM + idx) * EDIM + e];
    }
    d_X1[b * XS + t] = v;
}

// ---------------- 5) layer-1 interaction GEMM (FFMA2, BK=32, split-K=9) ----------------
__global__ void __launch_bounds__(256, 2) gemm1_kernel() {
    extern __shared__ __align__(16) char smem[];
    const uint32_t sb = smem_u32(smem);
    float* Wsm0 = (float*)(smem + OFF_W0);
    float* Wsm1 = (float*)(smem + OFF_W1);
    float2* Asm0 = (float2*)(smem + OFF_A0);
    float2* Asm1 = (float2*)(smem + OFF_A1);

    const int tid = threadIdx.x;
    const int colg = tid & 31;     // n pairs: colg*2 + s*64
    const int rowg = tid >> 5;     // m: rowg*8 .. +7
    const int mBase = blockIdx.x * BM;
    const int split = blockIdx.y;
    const int c0 = split * CPS;
    const int c1 = min(c0 + CPS, CHUNKS);
    const int am = tid & 63;       // A-build: fixed m per thread
    const int akg = tid >> 6;      // kk group 0..3 (8 kks each)
    const float* xr = d_X1 + (size_t)(mBase + am) * XS;

    unsigned long long acc[8][4];
#pragma unroll
    for (int a = 0; a < 8; a++)
#pragma unroll
        for (int s = 0; s < 4; s++) acc[a][s] = 0ULL;

    auto issueW = [&](int ch, int stg) {
        const char* g = (const char*)d_Wp1 + (size_t)ch * W_STG;
        const uint32_t s0 = sb + (stg ? OFF_W1 : OFF_W0);
#pragma unroll
        for (int q = 0; q < 8; q++) {
            const int off = (tid + q * 256) * 16;
            cpa16(s0 + off, g + off);
        }
        asm volatile("cp.async.commit_group;");
    };

    int tij[8];
    float xv[16];
    auto loadNext = [&](int ch) {
        const int rb = ch * BKC + akg * 8;
        const int4* t4 = (const int4*)(d_Tij + rb);
        int4 p0 = __ldg(t4);
        int4 p1 = __ldg(t4 + 1);
        tij[0] = p0.x; tij[1] = p0.y; tij[2] = p0.z; tij[3] = p0.w;
        tij[4] = p1.x; tij[5] = p1.y; tij[6] = p1.z; tij[7] = p1.w;
#pragma unroll
        for (int u = 0; u < 8; u++) {
            xv[2 * u]     = __ldg(xr + (tij[u] & 0xffff));
            xv[2 * u + 1] = __ldg(xr + (tij[u] >> 16));
        }
    };
    auto storeA = [&](int stg) {
        float2* dst = stg ? Asm1 : Asm0;
#pragma unroll
        for (int u = 0; u < 8; u++) {
            const float v = xv[2 * u] * xv[2 * u + 1];
            dst[(akg * 8 + u) * BM + am] = make_float2(v, v);
        }
    };

    // prologue
    issueW(c0, 0);
    loadNext(c0);
    storeA(0);
    asm volatile("cp.async.wait_group 0;");
    __syncthreads();

    for (int ch = c0; ch < c1; ch++) {
        const int buf = (ch - c0) & 1;
        const bool hasNext = (ch + 1 < c1);
        if (hasNext) {
            issueW(ch + 1, buf ^ 1);
            loadNext(ch + 1);      // LDGs in flight under the MMA block
        }
        const float* Wb = buf ? Wsm1 : Wsm0;
        const float2* Ab = buf ? Asm1 : Asm0;
#pragma unroll 8
        for (int kk = 0; kk < BKC; kk++) {
            const float2* ar = Ab + kk * BM + rowg * 8;
            ulonglong2 a01 = *reinterpret_cast<const ulonglong2*>(ar);
            ulonglong2 a23 = *reinterpret_cast<const ulonglong2*>(ar + 2);
            ulonglong2 a45 = *reinterpret_cast<const ulonglong2*>(ar + 4);
            ulonglong2 a67 = *reinterpret_cast<const ulonglong2*>(ar + 6);
            unsigned long long ap[8] = {a01.x, a01.y, a23.x, a23.y,
                                        a45.x, a45.y, a67.x, a67.y};
            unsigned long long wv[4];
            const float* wr = Wb + kk * NPAD + colg * 2;
#pragma unroll
            for (int s = 0; s < 4; s++)
                wv[s] = *reinterpret_cast<const unsigned long long*>(wr + s * 64);
#pragma unroll
            for (int tm = 0; tm < 8; tm++)
#pragma unroll
                for (int s = 0; s < 4; s++)
                    fma2(acc[tm][s], ap[tm], wv[s]);
        }
        if (hasNext) storeA(buf ^ 1);   // quick: products + 8 STS.64
        asm volatile("cp.async.wait_group 0;");
        __syncthreads();
    }

    // deterministic split-K partial store (coalesced float2; NPAD stride, no guard needed)
#pragma unroll
    for (int tm = 0; tm < 8; tm++) {
        const int row = mBase + rowg * 8 + tm;
        float* dst = d_Yp + ((size_t)split * BATCH + row) * NPAD;
#pragma unroll
        for (int s = 0; s < 4; s++) {
            const int col = colg * 2 + s * 64;
            *reinterpret_cast<float2*>(dst + col) = unpack2f(acc[tm][s]);
        }
    }
}

// ---------------- 6) reduce split-K partials + bias -> X2 (zero-padded to 224) ----------------
__global__ void reduce1_kernel(const float* __restrict__ b1) {
    int m = blockIdx.x;
    int c = threadIdx.x;
    float v = 0.f;
    if (c < FDIM) {
        v = b1[c];
#pragma unroll
        for (int p = 0; p < KSPLIT; p++)
            v += d_Yp[((size_t)p * BATCH + m) * NPAD + c];
    }
    d_X2[m * XS + c] = v;
}

// ---------------- 7) final: pooled = x2^T S2 x2 + sum(b2); sigmoid ----------------
#define RPB 4
__global__ void final_kernel(const float* __restrict__ out_w,
                             const float* __restrict__ out_b,
                             float* __restrict__ out) {
    __shared__ float xs[RPB][XS];
    __shared__ float red[8][RPB];
    const int tid = threadIdx.x;
    const int b0 = blockIdx.x * RPB;
    for (int idx = tid; idx < RPB * XS; idx += 256)
        xs[idx / XS][idx % XS] = d_X2[(size_t)(b0 + idx / XS) * XS + (idx % XS)];
    __syncthreads();

    float acc[RPB] = {0.f, 0.f, 0.f, 0.f};
    for (int r = tid; r < TRIP2; r += 256) {
        const float w = __ldg(&d_w2t[r]);
        const int p = __ldg(&d_Tij[r]);
        const int i = p & 0xffff, j = p >> 16;
#pragma unroll
        for (int q = 0; q < RPB; q++)
            acc[q] += xs[q][i] * xs[q][j] * w;
    }
    const int lane = tid & 31, warp = tid >> 5;
#pragma unroll
    for (int q = 0; q < RPB; q++) {
        float s = acc[q];
#pragma unroll
        for (int o = 16; o > 0; o >>= 1) s += __shfl_down_sync(0xffffffffu, s, o);
        if (lane == 0) red[warp][q] = s;
    }
    __syncthreads();
    if (tid < RPB) {
        float s = 0.f;
#pragma unroll
        for (int w = 0; w < 8; w++) s += red[w][tid];
        const float pooled = s + d_b2s;
        const float z = pooled * out_w[0] + out_b[0];
        out[b0 + tid] = 1.f / (1.f + expf(-z));
    }
}

extern "C" void kernel_launch(void* const* d_in, const int* in_sizes, int n_in,
                              void* d_out, int out_size) {
    const float* dense = (const float*)d_in[0];
    const int* sparse = (const int*)d_in[1];
    const float* emb = (const float*)d_in[2];
    const float* W1 = (const float*)d_in[3];
    const float* b1 = (const float*)d_in[4];
    const float* W2 = (const float*)d_in[5];
    const float* b2 = (const float*)d_in[6];
    // d_in[7..10]: attention weights — mathematically dead (softmax over size-1 axis == 1)
    const float* out_w = (const float*)d_in[11];
    const float* out_b = (const float*)d_in[12];
    float* out = (float*)d_out;

    cudaFuncSetAttribute(gemm1_kernel, cudaFuncAttributeMaxDynamicSharedMemorySize, SMEM_GEMM);

    make_pairs_kernel<<<1, 256>>>();
    pack1_kernel<<<TRIP2, 64>>>(W1);
    w2sum_kernel<<<(TRIP2 + 7) / 8, 256>>>(W2);
    b2sum_kernel<<<1, 256>>>(b2);
    build_x_kernel<<<BATCH, XS>>>(dense, sparse, emb);

    gemm1_kernel<<<dim3(BATCH / BM, KSPLIT), 256, SMEM_GEMM>>>();
    reduce1_kernel<<<BATCH, XS>>>(b1);
    final_kernel<<<BATCH / RPB, 256>>>(out_w, out_b, out);
}